// round 1
// baseline (speedup 1.0000x reference)
#include <cuda_runtime.h>
#include <cstdint>

#define Bsz     32768
#define Dd      1024
#define Cc      40
#define CCtot   80            // 40 fwd + 40 rev columns
#define RB      128           // rows per block
#define THREADS 256
#define KC      32            // k-chunk
#define NCHUNK  (Dd / KC)     // 32
#define SROW    34            // floats per smem tile row (bank-conflict pad, 8B aligned)

// ---- shared memory layout (floats), union of GEMM phase and chain phase ----
#define OFF_S0   0
#define OFF_S1   (RB * SROW)                    // 4352
#define OFF_W0   (2 * RB * SROW)                // 8704
#define OFF_W1   (2 * RB * SROW + CCtot * SROW) // 11424
#define GEMM_FLOATS (2 * RB * SROW + 2 * CCtot * SROW)  // 14144

#define BROW     81                              // bases row stride (odd -> conflict-free column scans)
#define OFF_BASES 0
#define OFF_WT   (RB * BROW)                     // 10368
#define OFF_BB   (OFF_WT + 2 * Cc * Cc)          // 13568
#define CHAIN_FLOATS (OFF_BB + 2 * Cc)           // 13648

#define SMEM_FLOATS (GEMM_FLOATS > CHAIN_FLOATS ? GEMM_FLOATS : CHAIN_FLOATS)
#define SMEM_BYTES  (SMEM_FLOATS * 4)            // 56576 B

extern __shared__ float sm[];

// packed f32x2 FMA: d.lo += a.lo*b.lo ; d.hi += a.hi*b.hi  (full-rate fp32 path on sm_103a)
__device__ __forceinline__ void fma2(unsigned long long& d,
                                     unsigned long long a,
                                     unsigned long long b) {
    asm("fma.rn.f32x2 %0, %1, %2, %0;" : "+l"(d) : "l"(a), "l"(b));
}

__global__ void __launch_bounds__(THREADS, 2)
bichain_kernel(const float* __restrict__ src,
               const float* __restrict__ W,   const float* __restrict__ b,
               const float* __restrict__ Wr,  const float* __restrict__ br,
               float* __restrict__ out) {
    const int tid  = threadIdx.x;
    const int warp = tid >> 5;
    const int lane = tid & 31;
    const int row0 = blockIdx.x * RB;

    uint32_t smbase;
    asm("{ .reg .u64 t; cvta.to.shared.u64 t, %1; cvt.u32.u64 %0, t; }"
        : "=r"(smbase) : "l"(sm));

    // issue one k-chunk (src tile 128x32, W tile 80x32) via cp.async 8B copies
    auto issue = [&](int chunk, int bufsel) {
        const int k0 = chunk * KC;
        const uint32_t sS = smbase + (bufsel ? OFF_S1 : OFF_S0) * 4;
        const uint32_t sW = smbase + (bufsel ? OFF_W1 : OFF_W0) * 4;
        // src: 128 rows * 16 x 8B segments = 2048 ops, 8 per thread
        #pragma unroll
        for (int i = 0; i < 8; ++i) {
            int idx = tid + i * THREADS;
            int r = idx >> 4, s = idx & 15;
            const float* g = src + (size_t)(row0 + r) * Dd + k0 + s * 2;
            uint32_t d = sS + (uint32_t)(r * SROW + s * 2) * 4u;
            asm volatile("cp.async.ca.shared.global [%0], [%1], 8;" :: "r"(d), "l"(g));
        }
        // W: 80 rows * 16 segments = 1280 ops, 5 per thread (rows >=40 come from W_rev)
        #pragma unroll
        for (int i = 0; i < 5; ++i) {
            int idx = tid + i * THREADS;
            int r = idx >> 4, s = idx & 15;
            const float* g = (r < Cc ? W  + (size_t)r        * (Dd + Cc)
                                     : Wr + (size_t)(r - Cc) * (Dd + Cc)) + k0 + s * 2;
            uint32_t d = sW + (uint32_t)(r * SROW + s * 2) * 4u;
            asm volatile("cp.async.ca.shared.global [%0], [%1], 8;" :: "r"(d), "l"(g));
        }
        asm volatile("cp.async.commit_group;");
    };

    // ---- GEMM phase: each warp owns 10 columns, each lane owns rows lane+32u ----
    unsigned long long acc[4][10];
    #pragma unroll
    for (int u = 0; u < 4; ++u)
        #pragma unroll
        for (int v = 0; v < 10; ++v) acc[u][v] = 0ull;

    issue(0, 0);
    const int c0 = warp * 10;

    for (int ch = 0; ch < NCHUNK; ++ch) {
        const int bsel = ch & 1;
        if (ch + 1 < NCHUNK) {
            issue(ch + 1, bsel ^ 1);
            asm volatile("cp.async.wait_group 1;");
        } else {
            asm volatile("cp.async.wait_group 0;");
        }
        __syncthreads();

        const unsigned long long* Sp =
            (const unsigned long long*)(sm + (bsel ? OFF_S1 : OFF_S0));
        const unsigned long long* Wp =
            (const unsigned long long*)(sm + (bsel ? OFF_W1 : OFF_W0));

        #pragma unroll 4
        for (int kk = 0; kk < KC / 2; ++kk) {
            unsigned long long a[4], w[10];
            #pragma unroll
            for (int u = 0; u < 4; ++u)
                a[u] = Sp[(size_t)(lane + 32 * u) * (SROW / 2) + kk];
            #pragma unroll
            for (int v = 0; v < 10; ++v)
                w[v] = Wp[(size_t)(c0 + v) * (SROW / 2) + kk];
            #pragma unroll
            for (int u = 0; u < 4; ++u)
                #pragma unroll
                for (int v = 0; v < 10; ++v)
                    fma2(acc[u][v], a[u], w[v]);
        }
        __syncthreads();
    }

    // ---- write bases (lo+hi combine) into smem union ----
    #pragma unroll
    for (int u = 0; u < 4; ++u) {
        const int r = lane + 32 * u;
        #pragma unroll
        for (int v = 0; v < 10; ++v) {
            float lo, hi;
            asm("mov.b64 {%0,%1}, %2;" : "=f"(lo), "=f"(hi) : "l"(acc[u][v]));
            sm[OFF_BASES + r * BROW + c0 + v] = lo + hi;
        }
    }
    // load triangular tail weights (W[:,1024:1064]) + biases into smem
    for (int idx = tid; idx < 2 * Cc * Cc; idx += THREADS) {
        const int chn = idx / (Cc * Cc);
        const int rem = idx - chn * Cc * Cc;
        const int i = rem / Cc, j = rem % Cc;
        const float* Wp = chn ? Wr : W;
        sm[OFF_WT + idx] = Wp[(size_t)i * (Dd + Cc) + Dd + j];
    }
    if (tid < 2 * Cc)
        sm[OFF_BB + tid] = (tid < Cc) ? b[tid] : br[tid - Cc];
    __syncthreads();

    // ---- sequential chain: 256 threads = 128 rows x 2 chains (fwd/rev) ----
    {
        const int row = tid >> 1, chn = tid & 1;
        float* my        = sm + OFF_BASES + row * BROW + chn * Cc;
        const float* wt  = sm + OFF_WT + chn * Cc * Cc;
        const float* bbc = sm + OFF_BB + chn * Cc;
        float s[Cc];
        #pragma unroll
        for (int i = 0; i < Cc; ++i) {
            float x = my[i] + bbc[i];
            #pragma unroll
            for (int j = 0; j < i; ++j)
                x = fmaf(s[j], wt[i * Cc + j], x);
            s[i] = 1.0f / (1.0f + __expf(-x));
            my[i] = s[i];   // scores overwrite bases in place (same thread, same slots)
        }
    }
    __syncthreads();

    // ---- combine fwd + reversed rev, write output ----
    #pragma unroll
    for (int i = 0; i < (RB * Cc) / THREADS; ++i) {   // 20 iterations
        const int idx = tid + i * THREADS;
        const int r = idx / Cc, c = idx % Cc;
        const float vf = sm[OFF_BASES + r * BROW + c];
        const float vr = sm[OFF_BASES + r * BROW + Cc + (Cc - 1 - c)];
        out[(size_t)(row0 + r) * Cc + c] = 0.5f * (vf + vr);
    }
}

extern "C" void kernel_launch(void* const* d_in, const int* in_sizes, int n_in,
                              void* d_out, int out_size) {
    const float* src = (const float*)d_in[0];
    // d_in[1] = attn_mask (unused by BiChain)
    const float* W   = (const float*)d_in[2];
    const float* b   = (const float*)d_in[3];
    const float* Wr  = (const float*)d_in[4];
    const float* br  = (const float*)d_in[5];
    float* out = (float*)d_out;

    cudaFuncSetAttribute(bichain_kernel,
                         cudaFuncAttributeMaxDynamicSharedMemorySize, SMEM_BYTES);
    bichain_kernel<<<Bsz / RB, THREADS, SMEM_BYTES>>>(src, W, b, Wr, br, out);
}

// round 3
// speedup vs baseline: 2.2928x; 2.2928x over previous
#include <cuda_runtime.h>
#include <cstdint>

#define Bsz     32768
#define Dd      1024
#define Cc      40
#define CT      80            // 40 fwd + 40 rev output columns
#define RB      128           // rows (M) per CTA
#define THREADS 256
#define KC      32            // k per chunk
#define NCH     (Dd / KC)     // 32
#define NSTAGE  3
#define PADK    36            // floats per smem row (bank: (36r+c)%32 = (4r+c)%32 -> lane-perfect)

#define A_FLOATS   (RB * PADK)            // 4608
#define B_FLOATS   (CT * PADK)            // 2880
#define STAGE_F    (A_FLOATS + B_FLOATS)  // 7488 floats = 29952 B
#define OFF0_F     256                    // 1024 B reserved at front
#define SMEM_BYTES ((OFF0_F + NSTAGE * STAGE_F) * 4)   // 90880 B -> 2 CTAs/SM

// epilogue overlay (after GEMM, aliases stage buffers)
#define BROW    81
#define EPI_BASE_F  OFF0_F
#define EPI_WT_F    (EPI_BASE_F + RB * BROW)          // bases 128x81
#define EPI_BB_F    (EPI_WT_F + 2 * Cc * Cc)

extern __shared__ float smf[];

__device__ __forceinline__ uint32_t tf32(float x) {
    uint32_t r;
    asm("cvt.rna.tf32.f32 %0, %1;" : "=r"(r) : "f"(x));
    return r;
}

__device__ __forceinline__ void mma_16x8x8(float* d, const uint32_t* a,
                                           const uint32_t* bfr) {
    asm volatile(
        "mma.sync.aligned.m16n8k8.row.col.f32.tf32.tf32.f32 "
        "{%0,%1,%2,%3}, {%4,%5,%6,%7}, {%8,%9}, {%0,%1,%2,%3};"
        : "+f"(d[0]), "+f"(d[1]), "+f"(d[2]), "+f"(d[3])
        : "r"(a[0]), "r"(a[1]), "r"(a[2]), "r"(a[3]), "r"(bfr[0]), "r"(bfr[1]));
}

__global__ void __launch_bounds__(THREADS, 2)
bichain_mma(const float* __restrict__ src,
            const float* __restrict__ W,  const float* __restrict__ b,
            const float* __restrict__ Wr, const float* __restrict__ br,
            float* __restrict__ out) {
    const int tid  = threadIdx.x;
    const int warp = tid >> 5;
    const int lane = tid & 31;
    const int row0 = blockIdx.x * RB;

    uint32_t smb;
    asm("{ .reg .u64 t; cvta.to.shared.u64 t, %1; cvt.u32.u64 %0, t; }"
        : "=r"(smb) : "l"(smf));

    // ---- cp.async one k-chunk into stage (all 256 threads), 16B copies ----
    auto issue = [&](int ch) {
        const int st = ch % NSTAGE;
        const int k0 = ch * KC;
        const uint32_t sA = smb + (OFF0_F + st * STAGE_F) * 4;
        const uint32_t sB = sA + A_FLOATS * 4;
        #pragma unroll
        for (int i = 0; i < 4; ++i) {                   // A: 128 rows x 8 segs
            int idx = tid + i * THREADS;
            int r = idx >> 3, seg = idx & 7;
            const float* g = src + (size_t)(row0 + r) * Dd + k0 + seg * 4;
            uint32_t d = sA + (uint32_t)(r * PADK + seg * 4) * 4u;
            asm volatile("cp.async.cg.shared.global [%0], [%1], 16;" :: "r"(d), "l"(g));
        }
        #pragma unroll
        for (int i = 0; i < 3; ++i) {                   // B: 80 rows x 8 segs
            int idx = tid + i * THREADS;
            if (idx < CT * 8) {
                int r = idx >> 3, seg = idx & 7;
                const float* g = (r < Cc ? W  + (size_t)r        * (Dd + Cc)
                                         : Wr + (size_t)(r - Cc) * (Dd + Cc))
                                 + k0 + seg * 4;
                uint32_t d = sB + (uint32_t)(r * PADK + seg * 4) * 4u;
                asm volatile("cp.async.cg.shared.global [%0], [%1], 16;" :: "r"(d), "l"(g));
            }
        }
        asm volatile("cp.async.commit_group;");
    };

    // warp tiling: 4 M-warps x 2 N-warps; each warp: 2 m-tiles (16) x 5 n-tiles (8)
    const int mw = warp >> 1;          // 0..3
    const int nw = warp & 1;           // 0..1
    const int qr = lane >> 2;          // lane/4
    const int qc = lane & 3;           // lane%4

    float acc[2][5][4];
    #pragma unroll
    for (int mm = 0; mm < 2; ++mm)
        #pragma unroll
        for (int t = 0; t < 5; ++t)
            #pragma unroll
            for (int e = 0; e < 4; ++e) acc[mm][t][e] = 0.f;

    issue(0); issue(1);

    for (int ch = 0; ch < NCH; ++ch) {
        if (ch < NCH - 1) asm volatile("cp.async.wait_group 1;");
        else              asm volatile("cp.async.wait_group 0;");
        __syncthreads();

        if (ch + 2 < NCH) issue(ch + 2);

        const float* Ap = smf + OFF0_F + (ch % NSTAGE) * STAGE_F;
        const float* Bp = Ap + A_FLOATS;

        #pragma unroll
        for (int kk = 0; kk < KC / 8; ++kk) {       // 4 k-steps
            const int kb = kk * 8;
            uint32_t afr[2][4], bfr[5][2];
            #pragma unroll
            for (int mm = 0; mm < 2; ++mm) {
                const int r = mw * 32 + mm * 16 + qr;
                afr[mm][0] = tf32(Ap[(r    ) * PADK + kb + qc    ]);
                afr[mm][1] = tf32(Ap[(r + 8) * PADK + kb + qc    ]);
                afr[mm][2] = tf32(Ap[(r    ) * PADK + kb + qc + 4]);
                afr[mm][3] = tf32(Ap[(r + 8) * PADK + kb + qc + 4]);
            }
            #pragma unroll
            for (int t = 0; t < 5; ++t) {
                const int n = nw * 40 + t * 8 + qr;
                bfr[t][0] = tf32(Bp[n * PADK + kb + qc    ]);
                bfr[t][1] = tf32(Bp[n * PADK + kb + qc + 4]);
            }
            #pragma unroll
            for (int mm = 0; mm < 2; ++mm)
                #pragma unroll
                for (int t = 0; t < 5; ++t)
                    mma_16x8x8(acc[mm][t], afr[mm], bfr[t]);
        }
        __syncthreads();
    }

    // ---- epilogue: accumulators -> smem bases[128][81] ----
    float* bases = smf + EPI_BASE_F;
    #pragma unroll
    for (int mm = 0; mm < 2; ++mm) {
        const int r = mw * 32 + mm * 16 + qr;
        #pragma unroll
        for (int t = 0; t < 5; ++t) {
            const int c = nw * 40 + t * 8 + qc * 2;
            bases[(r    ) * BROW + c    ] = acc[mm][t][0];
            bases[(r    ) * BROW + c + 1] = acc[mm][t][1];
            bases[(r + 8) * BROW + c    ] = acc[mm][t][2];
            bases[(r + 8) * BROW + c + 1] = acc[mm][t][3];
        }
    }

    // chain tail weights W[:,1024:1064] + biases
    float* wt = smf + EPI_WT_F;
    float* bb = smf + EPI_BB_F;
    for (int idx = tid; idx < 2 * Cc * Cc; idx += THREADS) {
        const int chn = idx / (Cc * Cc);
        const int rem = idx - chn * Cc * Cc;
        const int i = rem / Cc, j = rem % Cc;
        const float* Wp = chn ? Wr : W;
        wt[idx] = Wp[(size_t)i * (Dd + Cc) + Dd + j];
    }
    if (tid < 2 * Cc) bb[tid] = (tid < Cc) ? b[tid] : br[tid - Cc];
    __syncthreads();

    // ---- sequential chain: 256 threads = 128 rows x 2 chains ----
    {
        const int row = tid >> 1, chn = tid & 1;
        float* my        = bases + row * BROW + chn * Cc;
        const float* wtc = wt + chn * Cc * Cc;
        const float* bbc = bb + chn * Cc;
        float s[Cc];
        #pragma unroll
        for (int i = 0; i < Cc; ++i) {
            float x = my[i] + bbc[i];
            #pragma unroll
            for (int j = 0; j < i; ++j)
                x = fmaf(s[j], wtc[i * Cc + j], x);
            s[i] = 1.0f / (1.0f + __expf(-x));
            my[i] = s[i];
        }
    }
    __syncthreads();

    // ---- combine fwd + reversed rev, store ----
    #pragma unroll
    for (int i = 0; i < (RB * Cc) / THREADS; ++i) {   // 20
        const int idx = tid + i * THREADS;
        const int r = idx / Cc, c = idx % Cc;
        const float vf = bases[r * BROW + c];
        const float vr = bases[r * BROW + Cc + (Cc - 1 - c)];
        out[(size_t)(row0 + r) * Cc + c] = 0.5f * (vf + vr);
    }
}

extern "C" void kernel_launch(void* const* d_in, const int* in_sizes, int n_in,
                              void* d_out, int out_size) {
    const float* src = (const float*)d_in[0];
    // d_in[1] = attn_mask (unused)
    const float* W   = (const float*)d_in[2];
    const float* b   = (const float*)d_in[3];
    const float* Wr  = (const float*)d_in[4];
    const float* br  = (const float*)d_in[5];
    float* out = (float*)d_out;

    cudaFuncSetAttribute(bichain_mma,
                         cudaFuncAttributeMaxDynamicSharedMemorySize, SMEM_BYTES);
    bichain_mma<<<Bsz / RB, THREADS, SMEM_BYTES>>>(src, W, b, Wr, br, out);
}

// round 4
// speedup vs baseline: 2.3003x; 1.0033x over previous
#include <cuda_runtime.h>
#include <cstdint>

#define Bsz     32768
#define Dd      1024
#define Cc      40
#define CT      80            // 40 fwd + 40 rev output columns
#define RB      128           // rows (M) per CTA
#define THREADS 128           // 4 warps: 2 M-warps x 2 N-warps, each 4 m-tiles x 5 n-tiles
#define KC      32            // k per chunk
#define NCH     (Dd / KC)     // 32
#define NSTAGE  3
#define PADK    36            // floats per smem row -> bank (4r+c)%32, conflict-free

#define A_FLOATS   (RB * PADK)            // 4608
#define B_FLOATS   (CT * PADK)            // 2880
#define STAGE_F    (A_FLOATS + B_FLOATS)  // 7488 floats
#define OFF0_F     256
#define SMEM_BYTES ((OFF0_F + NSTAGE * STAGE_F) * 4)   // 90880 B -> 2 CTAs/SM

// epilogue overlay (aliases stage buffers after mainloop)
#define BROW    81
#define EPI_BASE_F  OFF0_F
#define EPI_WT_F    (EPI_BASE_F + RB * BROW)          // bases 128x81
#define EPI_BB_F    (EPI_WT_F + 2 * Cc * Cc)

extern __shared__ float smf[];

__device__ __forceinline__ uint32_t tf32(float x) {
    uint32_t r;
    asm("cvt.rna.tf32.f32 %0, %1;" : "=r"(r) : "f"(x));
    return r;
}

__device__ __forceinline__ void mma_16x8x8(float* d, const uint32_t* a,
                                           const uint32_t* bfr) {
    asm volatile(
        "mma.sync.aligned.m16n8k8.row.col.f32.tf32.tf32.f32 "
        "{%0,%1,%2,%3}, {%4,%5,%6,%7}, {%8,%9}, {%0,%1,%2,%3};"
        : "+f"(d[0]), "+f"(d[1]), "+f"(d[2]), "+f"(d[3])
        : "r"(a[0]), "r"(a[1]), "r"(a[2]), "r"(a[3]), "r"(bfr[0]), "r"(bfr[1]));
}

__global__ void __launch_bounds__(THREADS, 2)
bichain_mma4(const float* __restrict__ src,
             const float* __restrict__ W,  const float* __restrict__ b,
             const float* __restrict__ Wr, const float* __restrict__ br,
             float* __restrict__ out) {
    const int tid  = threadIdx.x;
    const int warp = tid >> 5;
    const int lane = tid & 31;
    const int row0 = blockIdx.x * RB;

    uint32_t smb;
    asm("{ .reg .u64 t; cvta.to.shared.u64 t, %1; cvt.u32.u64 %0, t; }"
        : "=r"(smb) : "l"(smf));

    // ---- per-thread cp.async source pointers (advance by KC per chunk) ----
    const int r8  = tid >> 3;          // 0..15
    const int seg = tid & 7;           // 0..7 (16B segments)
    const float* gA = src + (size_t)(row0 + r8) * Dd + seg * 4;
    const float* gB[5];
    #pragma unroll
    for (int i = 0; i < 5; ++i) {
        const int rb = r8 + 16 * i;    // 0..79
        gB[i] = (rb < Cc ? W  + (size_t)rb        * (Dd + Cc)
                         : Wr + (size_t)(rb - Cc) * (Dd + Cc)) + seg * 4;
    }

    auto issue = [&](int ch) {
        const int st = ch % NSTAGE;
        const uint32_t sA = smb + (OFF0_F + st * STAGE_F) * 4;
        const uint32_t sB = sA + A_FLOATS * 4;
        #pragma unroll
        for (int i = 0; i < 8; ++i) {                 // A: 128 rows x 8 segs
            const float* g = gA + (size_t)(16 * i) * Dd;
            uint32_t d = sA + (uint32_t)((r8 + 16 * i) * PADK + seg * 4) * 4u;
            asm volatile("cp.async.cg.shared.global [%0], [%1], 16;" :: "r"(d), "l"(g));
        }
        #pragma unroll
        for (int i = 0; i < 5; ++i) {                 // B: 80 rows x 8 segs
            uint32_t d = sB + (uint32_t)((r8 + 16 * i) * PADK + seg * 4) * 4u;
            asm volatile("cp.async.cg.shared.global [%0], [%1], 16;" :: "r"(d), "l"(gB[i]));
        }
        asm volatile("cp.async.commit_group;");
        gA += KC;
        #pragma unroll
        for (int i = 0; i < 5; ++i) gB[i] += KC;
    };

    // warp tiling
    const int mw = warp >> 1;          // 0..1 -> 64 rows each
    const int nw = warp & 1;           // 0..1 -> 40 cols each
    const int qr = lane >> 2;
    const int qc = lane & 3;

    int rowA[4], rowB[5];
    #pragma unroll
    for (int mt = 0; mt < 4; ++mt)
        rowA[mt] = (mw * 64 + mt * 16 + qr) * PADK + qc;
    #pragma unroll
    for (int t = 0; t < 5; ++t)
        rowB[t] = (nw * 40 + t * 8 + qr) * PADK + qc;

    float acc[4][5][4];
    #pragma unroll
    for (int mt = 0; mt < 4; ++mt)
        #pragma unroll
        for (int t = 0; t < 5; ++t)
            #pragma unroll
            for (int e = 0; e < 4; ++e) acc[mt][t][e] = 0.f;

    issue(0); issue(1);

    for (int ch = 0; ch < NCH; ++ch) {
        if (ch < NCH - 1) asm volatile("cp.async.wait_group 1;");
        else              asm volatile("cp.async.wait_group 0;");
        __syncthreads();                                  // single barrier per chunk
        if (ch + 2 < NCH) issue(ch + 2);                  // writes stage (ch-1)%3: free

        const float* Ap = smf + OFF0_F + (ch % NSTAGE) * STAGE_F;
        const float* Bp = Ap + A_FLOATS;

        #pragma unroll
        for (int kk = 0; kk < KC / 8; ++kk) {
            const int kb = kk * 8;
            uint32_t afr[4][4], bfr[5][2];
            #pragma unroll
            for (int mt = 0; mt < 4; ++mt) {
                afr[mt][0] = tf32(Ap[rowA[mt] + kb]);
                afr[mt][1] = tf32(Ap[rowA[mt] + 8 * PADK + kb]);
                afr[mt][2] = tf32(Ap[rowA[mt] + kb + 4]);
                afr[mt][3] = tf32(Ap[rowA[mt] + 8 * PADK + kb + 4]);
            }
            #pragma unroll
            for (int t = 0; t < 5; ++t) {
                bfr[t][0] = tf32(Bp[rowB[t] + kb]);
                bfr[t][1] = tf32(Bp[rowB[t] + kb + 4]);
            }
            #pragma unroll
            for (int mt = 0; mt < 4; ++mt)
                #pragma unroll
                for (int t = 0; t < 5; ++t)
                    mma_16x8x8(acc[mt][t], afr[mt], bfr[t]);
        }
    }
    __syncthreads();   // all warps done reading stages before overlay writes

    // ---- accumulators -> smem bases[128][81] ----
    float* bases = smf + EPI_BASE_F;
    #pragma unroll
    for (int mt = 0; mt < 4; ++mt) {
        const int r = mw * 64 + mt * 16 + qr;
        #pragma unroll
        for (int t = 0; t < 5; ++t) {
            const int c = nw * 40 + t * 8 + qc * 2;
            bases[(r    ) * BROW + c    ] = acc[mt][t][0];
            bases[(r    ) * BROW + c + 1] = acc[mt][t][1];
            bases[(r + 8) * BROW + c    ] = acc[mt][t][2];
            bases[(r + 8) * BROW + c + 1] = acc[mt][t][3];
        }
    }

    // chain tail weights W[:,1024:1064] + biases
    float* wt = smf + EPI_WT_F;
    float* bb = smf + EPI_BB_F;
    for (int idx = tid; idx < 2 * Cc * Cc; idx += THREADS) {
        const int chn = idx / (Cc * Cc);
        const int rem = idx - chn * Cc * Cc;
        const int i = rem / Cc, j = rem % Cc;
        const float* Wp = chn ? Wr : W;
        wt[idx] = Wp[(size_t)i * (Dd + Cc) + Dd + j];
    }
    if (tid < 2 * Cc) bb[tid] = (tid < Cc) ? b[tid] : br[tid - Cc];
    __syncthreads();

    // ---- sequential chains: each thread owns 1 row, runs BOTH chains interleaved ----
    {
        const int row = tid;
        float* my = bases + row * BROW;
        float sf[Cc], sr[Cc];
        #pragma unroll
        for (int i = 0; i < Cc; ++i) {
            float xf = my[i]      + bb[i];
            float xr = my[Cc + i] + bb[Cc + i];
            #pragma unroll
            for (int j = 0; j < i; ++j) {
                xf = fmaf(sf[j], wt[i * Cc + j],            xf);
                xr = fmaf(sr[j], wt[Cc * Cc + i * Cc + j],  xr);
            }
            sf[i] = 1.0f / (1.0f + __expf(-xf));
            sr[i] = 1.0f / (1.0f + __expf(-xr));
        }
        #pragma unroll
        for (int i = 0; i < Cc; ++i) {
            my[i]      = sf[i];
            my[Cc + i] = sr[i];
        }
    }
    __syncthreads();

    // ---- combine fwd + reversed rev, coalesced store ----
    #pragma unroll
    for (int it = 0; it < (RB * Cc) / THREADS; ++it) {   // 40
        const int idx = tid + it * THREADS;
        const int r = idx / Cc, c = idx - r * Cc;
        const float vf = bases[r * BROW + c];
        const float vr = bases[r * BROW + Cc + (Cc - 1 - c)];
        out[(size_t)(row0 + r) * Cc + c] = 0.5f * (vf + vr);
    }
}

extern "C" void kernel_launch(void* const* d_in, const int* in_sizes, int n_in,
                              void* d_out, int out_size) {
    const float* src = (const float*)d_in[0];
    // d_in[1] = attn_mask (unused)
    const float* W   = (const float*)d_in[2];
    const float* b   = (const float*)d_in[3];
    const float* Wr  = (const float*)d_in[4];
    const float* br  = (const float*)d_in[5];
    float* out = (float*)d_out;

    cudaFuncSetAttribute(bichain_mma4,
                         cudaFuncAttributeMaxDynamicSharedMemorySize, SMEM_BYTES);
    bichain_mma4<<<Bsz / RB, THREADS, SMEM_BYTES>>>(src, W, b, Wr, br, out);
}